// round 13
// baseline (speedup 1.0000x reference)
#include <cuda_runtime.h>
#include <cuda_fp16.h>
#include <cstdint>

#define N_NODES 50000
#define N_EDGES 800000
#define IN_DIM  256
#define HID     128
#define CAP     96          // per-node bucket capacity (Poisson(16) -> P(>=96) ~ 1e-40)

// -------- scratch (device globals; no allocations allowed) ------------------
__device__ __half g_fts [N_NODES * HID];     // gemm1 out, fp16 (read-only in seg1 phase)
__device__ __half g_z   [N_NODES * HID];     // seg1 out / gemm2 in, fp16
__device__ __half g_fts2[N_NODES * HID];     // gemm2 out / seg2 in, fp16
__device__ int    g_cnt[N_NODES];            // per-node edge count
__device__ int2   g_epack[N_NODES * CAP];    // (src, weight-bits) buckets

// -------- streams/events (host-side only; no device memory) -----------------
static cudaStream_t g_s2;
static cudaEvent_t  g_ev_fork, g_ev_csr, g_ev_sh0, g_ev_g2h0;
static struct StreamInit {
    StreamInit() {
        cudaStreamCreateWithFlags(&g_s2, cudaStreamNonBlocking);
        cudaEventCreateWithFlags(&g_ev_fork, cudaEventDisableTiming);
        cudaEventCreateWithFlags(&g_ev_csr,  cudaEventDisableTiming);
        cudaEventCreateWithFlags(&g_ev_sh0,  cudaEventDisableTiming);
        cudaEventCreateWithFlags(&g_ev_g2h0, cudaEventDisableTiming);
    }
} g_stream_init;

__device__ __forceinline__ uint32_t f2tf32(float f) {
    uint32_t r;
    asm("cvt.rna.tf32.f32 %0, %1;" : "=r"(r) : "f"(f));
    return r;
}

__device__ __forceinline__ void mma_tf32(float* d, const uint32_t* a, const uint32_t* b) {
    asm volatile(
        "mma.sync.aligned.m16n8k8.row.col.f32.tf32.tf32.f32 "
        "{%0,%1,%2,%3}, {%4,%5,%6,%7}, {%8,%9}, {%0,%1,%2,%3};"
        : "+f"(d[0]), "+f"(d[1]), "+f"(d[2]), "+f"(d[3])
        : "r"(a[0]), "r"(a[1]), "r"(a[2]), "r"(a[3]), "r"(b[0]), "r"(b[1]));
}

// 4-value load, fp32 or fp16 source, returns fp32
__device__ __forceinline__ float4 load4(const float* p) {
    return *reinterpret_cast<const float4*>(p);
}
__device__ __forceinline__ float4 load4(const __half* p) {
    uint2 u = *reinterpret_cast<const uint2*>(p);
    __half2 h0 = *reinterpret_cast<__half2*>(&u.x);
    __half2 h1 = *reinterpret_cast<__half2*>(&u.y);
    float2 f0 = __half22float2(h0), f1 = __half22float2(h1);
    return make_float4(f0.x, f0.y, f1.x, f1.y);
}

// ===========================================================================
// bucket build: zero counts -> scatter edges into per-node buckets
// ===========================================================================
__global__ void zero_int_kernel(int* __restrict__ p, int n) {
    int i = blockIdx.x * blockDim.x + threadIdx.x;
    if (i < n) p[i] = 0;
}

__global__ void fill_kernel(const int* __restrict__ ei, const float* __restrict__ ew,
                            int* __restrict__ cnt, int2* __restrict__ epack)
{
    int i = blockIdx.x * blockDim.x + threadIdx.x;
    if (i >= N_EDGES) return;
    int src   = __ldg(&ei[i]);
    int dst   = __ldg(&ei[N_EDGES + i]);
    int wbits = __float_as_int(__ldg(&ew[i]));
    int pos = atomicAdd(&cnt[dst], 1);
    if (pos < CAP)                                  // never triggers; OOB guard
        epack[(size_t)dst * CAP + pos] = make_int2(src, wbits);
}

// ===========================================================================
// tf32 mma.sync GEMM: C[M][128] = A[M][K] @ W[128][K]^T, fp16 output.
// CTA = 64x128 tile (2 CTAs/SM), 8 warps, warp tile 32x32 via m16n8k8.
// FRAGMENT-ORDER SMEM: A tile stored as [mb:4][kk:4][lane:32][reg:4] so a
// thread's whole m16k8 A-fragment is one LDS.128; W as [nb:16][kk:4][lane:32]
// [reg:2] -> one LDS.64 per n8k8 fragment. Reads are conflict-free.
// ===========================================================================
#define A_IDX(mb, kk, ln, rg)  ((((mb) * 4 + (kk)) * 32 + (ln)) * 4 + (rg))
#define W_IDX(nb, kk, ln, rg)  ((((nb) * 4 + (kk)) * 32 + (ln)) * 2 + (rg))

template <int K, typename AT>
__global__ __launch_bounds__(256, 2) void gemm_mma_kernel(
    const AT* __restrict__ A, const float* __restrict__ W,
    __half* __restrict__ C, int M)
{
    constexpr int NC = K / 32;
    __shared__ uint32_t Asf[4 * 4 * 32 * 4];    //  8 KB
    __shared__ uint32_t Wsf[16 * 4 * 32 * 2];   // 16 KB

    const int tid  = threadIdx.x;
    const int lane = tid & 31;
    const int w    = tid >> 5;
    const int m0   = blockIdx.x * 64;
    const int wr   = (w & 1) * 32;    // warp row base (0/32)
    const int wc   = (w >> 1) * 32;   // warp col base (0..96)
    const int grp  = lane >> 2;       // 0..7
    const int tig  = lane & 3;        // 0..3

    float acc[2][4][4];
#pragma unroll
    for (int mt = 0; mt < 2; mt++)
#pragma unroll
        for (int nt = 0; nt < 4; nt++)
#pragma unroll
            for (int j = 0; j < 4; j++) acc[mt][nt][j] = 0.f;

    const int lr = tid >> 3;          // 0..31 (tile row slot)
    const int lc = (tid & 7) * 4;     // 0,4,...,28 (k-col base within chunk)
    const int kkw  = lc >> 3;         // kk of this thread's 4 cols
    const int half = (lc & 4) >> 2;   // col-half within k8

    float4 pa[2], pw[4];
#pragma unroll
    for (int t = 0; t < 2; t++) {
        int m = m0 + lr + t * 32;
        pa[t] = (m < M) ? load4(&A[(size_t)m * K + lc]) : make_float4(0.f, 0.f, 0.f, 0.f);
    }
#pragma unroll
    for (int t = 0; t < 4; t++)
        pw[t] = load4(&W[(size_t)(lr + t * 32) * K + lc]);

#pragma unroll 1
    for (int ch = 0; ch < NC; ch++) {
        if (ch) __syncthreads();
        // ---- scatter loaded values into fragment-order SMEM ----
#pragma unroll
        for (int t = 0; t < 2; t++) {
            int ra = lr + t * 32;                 // 0..63
            int mb = ra >> 4, rr = ra & 15;
            int rg = half * 2 + (rr >> 3);        // fragment reg index
            int lb = (rr & 7) * 4;                // lane base (grp*4)
            float v[4] = { pa[t].x, pa[t].y, pa[t].z, pa[t].w };
#pragma unroll
            for (int i = 0; i < 4; i++)
                Asf[A_IDX(mb, kkw, lb + i, rg)] = f2tf32(v[i]);
        }
#pragma unroll
        for (int t = 0; t < 4; t++) {
            int rw = lr + t * 32;                 // 0..127
            int nb = rw >> 3;
            int lb = (rw & 7) * 4;
            float v[4] = { pw[t].x, pw[t].y, pw[t].z, pw[t].w };
#pragma unroll
            for (int i = 0; i < 4; i++)
                Wsf[W_IDX(nb, kkw, lb + i, half)] = f2tf32(v[i]);
        }
        __syncthreads();

        if (ch + 1 < NC) {            // prefetch next chunk (overlaps MMAs)
            const int ko = (ch + 1) * 32 + lc;
#pragma unroll
            for (int t = 0; t < 2; t++) {
                int m = m0 + lr + t * 32;
                pa[t] = (m < M) ? load4(&A[(size_t)m * K + ko]) : make_float4(0.f, 0.f, 0.f, 0.f);
            }
#pragma unroll
            for (int t = 0; t < 4; t++)
                pw[t] = load4(&W[(size_t)(lr + t * 32) * K + ko]);
        }

        // ---- MMAs: vectorized fragment loads ----
#pragma unroll
        for (int kk = 0; kk < 4; kk++) {
            uint32_t af[2][4], bf[4][2];
#pragma unroll
            for (int mt = 0; mt < 2; mt++) {
                int mb = (wr >> 4) + mt;
                uint4 fa = *reinterpret_cast<uint4*>(&Asf[A_IDX(mb, kk, lane, 0)]);
                af[mt][0] = fa.x; af[mt][1] = fa.y; af[mt][2] = fa.z; af[mt][3] = fa.w;
            }
#pragma unroll
            for (int nt = 0; nt < 4; nt++) {
                int nb = (wc >> 3) + nt;
                uint2 fb = *reinterpret_cast<uint2*>(&Wsf[W_IDX(nb, kk, lane, 0)]);
                bf[nt][0] = fb.x; bf[nt][1] = fb.y;
            }
#pragma unroll
            for (int mt = 0; mt < 2; mt++)
#pragma unroll
                for (int nt = 0; nt < 4; nt++)
                    mma_tf32(acc[mt][nt], af[mt], bf[nt]);
        }
    }

    // epilogue: fp16 store (half2 per fragment pair)
#pragma unroll
    for (int mt = 0; mt < 2; mt++) {
        int r0 = m0 + wr + mt * 16 + grp;
        int r1 = r0 + 8;
#pragma unroll
        for (int nt = 0; nt < 4; nt++) {
            int col = wc + nt * 8 + tig * 2;
            if (r0 < M)
                *reinterpret_cast<__half2*>(&C[(size_t)r0 * 128 + col]) =
                    __floats2half2_rn(acc[mt][nt][0], acc[mt][nt][1]);
            if (r1 < M)
                *reinterpret_cast<__half2*>(&C[(size_t)r1 * 128 + col]) =
                    __floats2half2_rn(acc[mt][nt][2], acc[mt][nt][3]);
        }
    }
}

// ===========================================================================
// Fused segmented gather-sum + bias + PReLU (one warp per dst node).
// fp16 feature rows (256B): lane gathers uint2 (4 halves) -> fp32 accumulate.
// OUT16: write fp16 (z, feeds gemm2) or fp32 (final output).
// ===========================================================================
template <bool OUT16>
__global__ __launch_bounds__(256) void seg_kernel(
    const __half* __restrict__ fts,
    const int*    __restrict__ cnt,
    const int2*   __restrict__ epack,
    const float*  __restrict__ b,
    const float*  __restrict__ a,
    void*         __restrict__ out,
    int node_base, int n_nodes)
{
    int widx = (blockIdx.x * blockDim.x + threadIdx.x) >> 5;
    int lane = threadIdx.x & 31;
    if (widx >= n_nodes) return;
    const int node = node_base + widx;

    const int deg = min(cnt[node], CAP);
    const int2* ep = epack + (size_t)node * CAP;

    float4 acc = make_float4(0.f, 0.f, 0.f, 0.f);

#pragma unroll 1
    for (int c0 = 0; c0 < deg; c0 += 32) {
        const int n = min(deg - c0, 32);
        int2 ed = (lane < n) ? __ldg(&ep[c0 + lane]) : make_int2(0, 0);

        int e = 0;
        for (; e + 3 < n; e += 4) {
            int   s0 = __shfl_sync(0xFFFFFFFFu, ed.x, e);
            int   s1 = __shfl_sync(0xFFFFFFFFu, ed.x, e + 1);
            int   s2 = __shfl_sync(0xFFFFFFFFu, ed.x, e + 2);
            int   s3 = __shfl_sync(0xFFFFFFFFu, ed.x, e + 3);
            float w0 = __int_as_float(__shfl_sync(0xFFFFFFFFu, ed.y, e));
            float w1 = __int_as_float(__shfl_sync(0xFFFFFFFFu, ed.y, e + 1));
            float w2 = __int_as_float(__shfl_sync(0xFFFFFFFFu, ed.y, e + 2));
            float w3 = __int_as_float(__shfl_sync(0xFFFFFFFFu, ed.y, e + 3));
            float4 v0 = load4(fts + (size_t)s0 * HID + lane * 4);
            float4 v1 = load4(fts + (size_t)s1 * HID + lane * 4);
            float4 v2 = load4(fts + (size_t)s2 * HID + lane * 4);
            float4 v3 = load4(fts + (size_t)s3 * HID + lane * 4);
            acc.x += w0 * v0.x + w1 * v1.x + w2 * v2.x + w3 * v3.x;
            acc.y += w0 * v0.y + w1 * v1.y + w2 * v2.y + w3 * v3.y;
            acc.z += w0 * v0.z + w1 * v1.z + w2 * v2.z + w3 * v3.z;
            acc.w += w0 * v0.w + w1 * v1.w + w2 * v2.w + w3 * v3.w;
        }
        for (; e < n; e++) {
            int   s0 = __shfl_sync(0xFFFFFFFFu, ed.x, e);
            float w0 = __int_as_float(__shfl_sync(0xFFFFFFFFu, ed.y, e));
            float4 v0 = load4(fts + (size_t)s0 * HID + lane * 4);
            acc.x += w0 * v0.x; acc.y += w0 * v0.y;
            acc.z += w0 * v0.z; acc.w += w0 * v0.w;
        }
    }

    float alpha = a[0];
    float4 bb = reinterpret_cast<const float4*>(b)[lane];
    acc.x += bb.x; acc.y += bb.y; acc.z += bb.z; acc.w += bb.w;
    acc.x = acc.x >= 0.f ? acc.x : alpha * acc.x;
    acc.y = acc.y >= 0.f ? acc.y : alpha * acc.y;
    acc.z = acc.z >= 0.f ? acc.z : alpha * acc.z;
    acc.w = acc.w >= 0.f ? acc.w : alpha * acc.w;

    if (OUT16) {
        __half2 h0 = __floats2half2_rn(acc.x, acc.y);
        __half2 h1 = __floats2half2_rn(acc.z, acc.w);
        uint2 st;
        st.x = *reinterpret_cast<uint32_t*>(&h0);
        st.y = *reinterpret_cast<uint32_t*>(&h1);
        reinterpret_cast<uint2*>(reinterpret_cast<__half*>(out) + (size_t)node * HID)[lane] = st;
    } else {
        reinterpret_cast<float4*>(reinterpret_cast<float*>(out) + (size_t)node * HID)[lane] = acc;
    }
}

// ===========================================================================
extern "C" void kernel_launch(void* const* d_in, const int* in_sizes, int n_in,
                              void* d_out, int out_size)
{
    const float* x  = (const float*)d_in[0];
    const int*   ei = (const int*)  d_in[1];
    const float* ew = (const float*)d_in[2];
    const float* W1 = (const float*)d_in[3];
    const float* b1 = (const float*)d_in[4];
    const float* a1 = (const float*)d_in[5];
    const float* W2 = (const float*)d_in[6];
    const float* b2 = (const float*)d_in[7];
    const float* a2 = (const float*)d_in[8];
    float* out = (float*)d_out;

    __half *fts, *z, *fts2;
    int *cnt;
    int2 *epack;
    cudaGetSymbolAddress((void**)&fts,   g_fts);
    cudaGetSymbolAddress((void**)&z,     g_z);
    cudaGetSymbolAddress((void**)&fts2,  g_fts2);
    cudaGetSymbolAddress((void**)&cnt,   g_cnt);
    cudaGetSymbolAddress((void**)&epack, g_epack);

    const int EB  = (N_EDGES + 255) / 256;
    const int NBK = (N_NODES + 255) / 256;
    const int GB  = (N_NODES + 63) / 64;               // 782 tiles (BM=64)

    // node halves for the seg1/gemm2 pipeline (64-divisible split)
    const int H0 = 25088;
    const int H1 = N_NODES - H0;
    const int G0 = H0 / 64;
    const int G1 = (H1 + 63) / 64;
    const int SGB0 = (H0 * 32 + 255) / 256;
    const int SGB1 = (H1 * 32 + 255) / 256;
    const int SGBF = (N_NODES * 32 + 255) / 256;

    // ---- fork: bucket build on g_s2, concurrent with gemm1 on stream 0 ----
    cudaEventRecord(g_ev_fork, 0);
    cudaStreamWaitEvent(g_s2, g_ev_fork, 0);

    zero_int_kernel<<<NBK, 256, 0, g_s2>>>(cnt, N_NODES);
    fill_kernel<<<EB, 256, 0, g_s2>>>(ei, ew, cnt, epack);
    cudaEventRecord(g_ev_csr, g_s2);

    gemm_mma_kernel<IN_DIM, float><<<GB, 256>>>(x, W1, fts, N_NODES);

    // ---- join: seg1 needs buckets + gemm1 ----
    cudaStreamWaitEvent(0, g_ev_csr, 0);

    // seg1 half0 -> z[0:H0] (fp16); gemm2 half0 (z->fts2) on s2 concurrently
    // with seg1 half1 (reads fts only; fts2 disjoint -> race-free).
    seg_kernel<true><<<SGB0, 256>>>(fts, cnt, epack, b1, a1, z, 0, H0);
    cudaEventRecord(g_ev_sh0, 0);
    cudaStreamWaitEvent(g_s2, g_ev_sh0, 0);
    gemm_mma_kernel<HID, __half><<<G0, 256, 0, g_s2>>>(z, W2, fts2, H0);
    cudaEventRecord(g_ev_g2h0, g_s2);

    seg_kernel<true><<<SGB1, 256>>>(fts, cnt, epack, b1, a1, z, H0, H1);
    gemm_mma_kernel<HID, __half><<<G1, 256>>>(z + (size_t)H0 * HID, W2,
                                              fts2 + (size_t)H0 * HID, H1);

    // seg2 needs both gemm2 halves; writes fp32 to out
    cudaStreamWaitEvent(0, g_ev_g2h0, 0);
    seg_kernel<false><<<SGBF, 256>>>(fts2, cnt, epack, b2, a2, out, 0, N_NODES);
}

// round 14
// speedup vs baseline: 1.1744x; 1.1744x over previous
#include <cuda_runtime.h>
#include <cuda_fp16.h>
#include <cstdint>

#define N_NODES 50000
#define N_EDGES 800000
#define IN_DIM  256
#define HID     128
#define CAP     96          // per-node bucket capacity (Poisson(16) -> P(>=96) ~ 1e-40)

// -------- scratch (device globals; no allocations allowed) ------------------
__device__ __half g_fts [N_NODES * HID];     // gemm1 out, fp16 (read-only in seg1 phase)
__device__ __half g_z   [N_NODES * HID];     // seg1 out / gemm2 in, fp16
__device__ __half g_fts2[N_NODES * HID];     // gemm2 out / seg2 in, fp16
__device__ int    g_cnt[N_NODES];            // per-node edge count
__device__ int2   g_epack[N_NODES * CAP];    // (src, weight-bits) buckets

// -------- streams/events (host-side only; no device memory) -----------------
static cudaStream_t g_s2;
static cudaEvent_t  g_ev_fork, g_ev_csr, g_ev_sh0, g_ev_g2h0;
static struct StreamInit {
    StreamInit() {
        cudaStreamCreateWithFlags(&g_s2, cudaStreamNonBlocking);
        cudaEventCreateWithFlags(&g_ev_fork, cudaEventDisableTiming);
        cudaEventCreateWithFlags(&g_ev_csr,  cudaEventDisableTiming);
        cudaEventCreateWithFlags(&g_ev_sh0,  cudaEventDisableTiming);
        cudaEventCreateWithFlags(&g_ev_g2h0, cudaEventDisableTiming);
    }
} g_stream_init;

__device__ __forceinline__ uint32_t f2tf32(float f) {
    uint32_t r;
    asm("cvt.rna.tf32.f32 %0, %1;" : "=r"(r) : "f"(f));
    return r;
}

__device__ __forceinline__ void mma_tf32(float* d, const uint32_t* a, const uint32_t* b) {
    asm volatile(
        "mma.sync.aligned.m16n8k8.row.col.f32.tf32.tf32.f32 "
        "{%0,%1,%2,%3}, {%4,%5,%6,%7}, {%8,%9}, {%0,%1,%2,%3};"
        : "+f"(d[0]), "+f"(d[1]), "+f"(d[2]), "+f"(d[3])
        : "r"(a[0]), "r"(a[1]), "r"(a[2]), "r"(a[3]), "r"(b[0]), "r"(b[1]));
}

// 4-value load, fp32 or fp16 source, returns fp32
__device__ __forceinline__ float4 load4(const float* p) {
    return *reinterpret_cast<const float4*>(p);
}
__device__ __forceinline__ float4 load4(const __half* p) {
    uint2 u = *reinterpret_cast<const uint2*>(p);
    __half2 h0 = *reinterpret_cast<__half2*>(&u.x);
    __half2 h1 = *reinterpret_cast<__half2*>(&u.y);
    float2 f0 = __half22float2(h0), f1 = __half22float2(h1);
    return make_float4(f0.x, f0.y, f1.x, f1.y);
}

// 8 halves (uint4) -> 8 floats, accumulate with weight
__device__ __forceinline__ void acc8(float* acc, uint4 u, float w) {
    __half2 h0 = *reinterpret_cast<__half2*>(&u.x);
    __half2 h1 = *reinterpret_cast<__half2*>(&u.y);
    __half2 h2 = *reinterpret_cast<__half2*>(&u.z);
    __half2 h3 = *reinterpret_cast<__half2*>(&u.w);
    float2 f0 = __half22float2(h0), f1 = __half22float2(h1);
    float2 f2 = __half22float2(h2), f3 = __half22float2(h3);
    acc[0] += w * f0.x; acc[1] += w * f0.y;
    acc[2] += w * f1.x; acc[3] += w * f1.y;
    acc[4] += w * f2.x; acc[5] += w * f2.y;
    acc[6] += w * f3.x; acc[7] += w * f3.y;
}

// ===========================================================================
// bucket build: zero counts -> scatter edges into per-node buckets
// ===========================================================================
__global__ void zero_int_kernel(int* __restrict__ p, int n) {
    int i = blockIdx.x * blockDim.x + threadIdx.x;
    if (i < n) p[i] = 0;
}

__global__ void fill_kernel(const int* __restrict__ ei, const float* __restrict__ ew,
                            int* __restrict__ cnt, int2* __restrict__ epack)
{
    int i = blockIdx.x * blockDim.x + threadIdx.x;
    if (i >= N_EDGES) return;
    int src   = __ldg(&ei[i]);
    int dst   = __ldg(&ei[N_EDGES + i]);
    int wbits = __float_as_int(__ldg(&ew[i]));
    int pos = atomicAdd(&cnt[dst], 1);
    if (pos < CAP)                                  // never triggers; OOB guard
        epack[(size_t)dst * CAP + pos] = make_int2(src, wbits);
}

// ===========================================================================
// tf32 mma.sync GEMM (R12 form): C[M][128] = A[M][K] @ W[128][K]^T, fp16 out.
// CTA = 64x128 tile (2 CTAs/SM), 8 warps, warp tile 32x32 via m16n8k8.
// ===========================================================================
#define SSTRIDE 36

template <int K, typename AT>
__global__ __launch_bounds__(256, 2) void gemm_mma_kernel(
    const AT* __restrict__ A, const float* __restrict__ W,
    __half* __restrict__ C, int M)
{
    constexpr int NC = K / 32;
    __shared__ uint32_t As[64 * SSTRIDE];
    __shared__ uint32_t Ws[128 * SSTRIDE];

    const int tid  = threadIdx.x;
    const int lane = tid & 31;
    const int w    = tid >> 5;
    const int m0   = blockIdx.x * 64;
    const int wr   = (w & 1) * 32;
    const int wc   = (w >> 1) * 32;
    const int grp  = lane >> 2;
    const int tig  = lane & 3;

    float acc[2][4][4];
#pragma unroll
    for (int mt = 0; mt < 2; mt++)
#pragma unroll
        for (int nt = 0; nt < 4; nt++)
#pragma unroll
            for (int j = 0; j < 4; j++) acc[mt][nt][j] = 0.f;

    const int lr = tid >> 3;
    const int lc = (tid & 7) * 4;

    float4 pa[2], pw[4];
#pragma unroll
    for (int t = 0; t < 2; t++) {
        int m = m0 + lr + t * 32;
        pa[t] = (m < M) ? load4(&A[(size_t)m * K + lc]) : make_float4(0.f, 0.f, 0.f, 0.f);
    }
#pragma unroll
    for (int t = 0; t < 4; t++)
        pw[t] = load4(&W[(size_t)(lr + t * 32) * K + lc]);

#pragma unroll 1
    for (int ch = 0; ch < NC; ch++) {
        if (ch) __syncthreads();
#pragma unroll
        for (int t = 0; t < 2; t++) {
            uint32_t* ap = &As[(lr + t * 32) * SSTRIDE + lc];
            ap[0] = f2tf32(pa[t].x); ap[1] = f2tf32(pa[t].y);
            ap[2] = f2tf32(pa[t].z); ap[3] = f2tf32(pa[t].w);
        }
#pragma unroll
        for (int t = 0; t < 4; t++) {
            uint32_t* wp = &Ws[(lr + t * 32) * SSTRIDE + lc];
            wp[0] = f2tf32(pw[t].x); wp[1] = f2tf32(pw[t].y);
            wp[2] = f2tf32(pw[t].z); wp[3] = f2tf32(pw[t].w);
        }
        __syncthreads();

        if (ch + 1 < NC) {
            const int ko = (ch + 1) * 32 + lc;
#pragma unroll
            for (int t = 0; t < 2; t++) {
                int m = m0 + lr + t * 32;
                pa[t] = (m < M) ? load4(&A[(size_t)m * K + ko]) : make_float4(0.f, 0.f, 0.f, 0.f);
            }
#pragma unroll
            for (int t = 0; t < 4; t++)
                pw[t] = load4(&W[(size_t)(lr + t * 32) * K + ko]);
        }

#pragma unroll
        for (int kk = 0; kk < 4; kk++) {
            uint32_t af[2][4], bf[4][2];
#pragma unroll
            for (int mt = 0; mt < 2; mt++) {
                int rb = wr + mt * 16;
                af[mt][0] = As[(rb + grp)     * SSTRIDE + kk * 8 + tig];
                af[mt][1] = As[(rb + grp + 8) * SSTRIDE + kk * 8 + tig];
                af[mt][2] = As[(rb + grp)     * SSTRIDE + kk * 8 + tig + 4];
                af[mt][3] = As[(rb + grp + 8) * SSTRIDE + kk * 8 + tig + 4];
            }
#pragma unroll
            for (int nt = 0; nt < 4; nt++) {
                int nb = wc + nt * 8 + grp;
                bf[nt][0] = Ws[nb * SSTRIDE + kk * 8 + tig];
                bf[nt][1] = Ws[nb * SSTRIDE + kk * 8 + tig + 4];
            }
#pragma unroll
            for (int mt = 0; mt < 2; mt++)
#pragma unroll
                for (int nt = 0; nt < 4; nt++)
                    mma_tf32(acc[mt][nt], af[mt], bf[nt]);
        }
    }

#pragma unroll
    for (int mt = 0; mt < 2; mt++) {
        int r0 = m0 + wr + mt * 16 + grp;
        int r1 = r0 + 8;
#pragma unroll
        for (int nt = 0; nt < 4; nt++) {
            int col = wc + nt * 8 + tig * 2;
            if (r0 < M)
                *reinterpret_cast<__half2*>(&C[(size_t)r0 * 128 + col]) =
                    __floats2half2_rn(acc[mt][nt][0], acc[mt][nt][1]);
            if (r1 < M)
                *reinterpret_cast<__half2*>(&C[(size_t)r1 * 128 + col]) =
                    __floats2half2_rn(acc[mt][nt][2], acc[mt][nt][3]);
        }
    }
}

// ===========================================================================
// Fused segmented gather-sum + bias + PReLU.
// HALF-WARP (16 lanes) per dst node: lane gathers uint4 (8 halves = 16B),
// one warp advances TWO edges per load instruction. Descriptors loaded
// coalesced (16/half-warp) and broadcast via width-16 shfl.
// ===========================================================================
template <bool OUT16>
__global__ __launch_bounds__(256) void seg_kernel(
    const __half* __restrict__ fts,
    const int*    __restrict__ cnt,
    const int2*   __restrict__ epack,
    const float*  __restrict__ b,
    const float*  __restrict__ a,
    void*         __restrict__ out,
    int node_base, int n_nodes)
{
    int hw = (blockIdx.x * blockDim.x + threadIdx.x) >> 4;   // half-warp index
    int hl = threadIdx.x & 15;                               // lane within half
    if (hw >= n_nodes) return;
    const int node = node_base + hw;

    const int deg = min(cnt[node], CAP);
    const int2* ep = epack + (size_t)node * CAP;

    float acc[8];
#pragma unroll
    for (int i = 0; i < 8; i++) acc[i] = 0.f;

#pragma unroll 1
    for (int c0 = 0; c0 < deg; c0 += 16) {
        const int n = min(deg - c0, 16);
        // coalesced 128B load per half-warp: lane e holds edge c0+e
        int2 ed = (hl < n) ? __ldg(&ep[c0 + hl]) : make_int2(0, 0);

        int e = 0;
        for (; e + 3 < n; e += 4) {
            int   s0 = __shfl_sync(0xFFFFFFFFu, ed.x, e,     16);
            int   s1 = __shfl_sync(0xFFFFFFFFu, ed.x, e + 1, 16);
            int   s2 = __shfl_sync(0xFFFFFFFFu, ed.x, e + 2, 16);
            int   s3 = __shfl_sync(0xFFFFFFFFu, ed.x, e + 3, 16);
            float w0 = __int_as_float(__shfl_sync(0xFFFFFFFFu, ed.y, e,     16));
            float w1 = __int_as_float(__shfl_sync(0xFFFFFFFFu, ed.y, e + 1, 16));
            float w2 = __int_as_float(__shfl_sync(0xFFFFFFFFu, ed.y, e + 2, 16));
            float w3 = __int_as_float(__shfl_sync(0xFFFFFFFFu, ed.y, e + 3, 16));
            uint4 v0 = reinterpret_cast<const uint4*>(fts + (size_t)s0 * HID)[hl];
            uint4 v1 = reinterpret_cast<const uint4*>(fts + (size_t)s1 * HID)[hl];
            uint4 v2 = reinterpret_cast<const uint4*>(fts + (size_t)s2 * HID)[hl];
            uint4 v3 = reinterpret_cast<const uint4*>(fts + (size_t)s3 * HID)[hl];
            acc8(acc, v0, w0); acc8(acc, v1, w1);
            acc8(acc, v2, w2); acc8(acc, v3, w3);
        }
        for (; e < n; e++) {
            int   s0 = __shfl_sync(0xFFFFFFFFu, ed.x, e, 16);
            float w0 = __int_as_float(__shfl_sync(0xFFFFFFFFu, ed.y, e, 16));
            uint4 v0 = reinterpret_cast<const uint4*>(fts + (size_t)s0 * HID)[hl];
            acc8(acc, v0, w0);
        }
    }

    float alpha = a[0];
    float4 bb0 = load4(&b[hl * 8]);
    float4 bb1 = load4(&b[hl * 8 + 4]);
    acc[0] += bb0.x; acc[1] += bb0.y; acc[2] += bb0.z; acc[3] += bb0.w;
    acc[4] += bb1.x; acc[5] += bb1.y; acc[6] += bb1.z; acc[7] += bb1.w;
#pragma unroll
    for (int i = 0; i < 8; i++)
        acc[i] = acc[i] >= 0.f ? acc[i] : alpha * acc[i];

    if (OUT16) {
        __half2 h0 = __floats2half2_rn(acc[0], acc[1]);
        __half2 h1 = __floats2half2_rn(acc[2], acc[3]);
        __half2 h2 = __floats2half2_rn(acc[4], acc[5]);
        __half2 h3 = __floats2half2_rn(acc[6], acc[7]);
        uint4 st;
        st.x = *reinterpret_cast<uint32_t*>(&h0);
        st.y = *reinterpret_cast<uint32_t*>(&h1);
        st.z = *reinterpret_cast<uint32_t*>(&h2);
        st.w = *reinterpret_cast<uint32_t*>(&h3);
        reinterpret_cast<uint4*>(reinterpret_cast<__half*>(out) + (size_t)node * HID)[hl] = st;
    } else {
        float* op = reinterpret_cast<float*>(out) + (size_t)node * HID + hl * 8;
        *reinterpret_cast<float4*>(op)     = make_float4(acc[0], acc[1], acc[2], acc[3]);
        *reinterpret_cast<float4*>(op + 4) = make_float4(acc[4], acc[5], acc[6], acc[7]);
    }
}

// ===========================================================================
extern "C" void kernel_launch(void* const* d_in, const int* in_sizes, int n_in,
                              void* d_out, int out_size)
{
    const float* x  = (const float*)d_in[0];
    const int*   ei = (const int*)  d_in[1];
    const float* ew = (const float*)d_in[2];
    const float* W1 = (const float*)d_in[3];
    const float* b1 = (const float*)d_in[4];
    const float* a1 = (const float*)d_in[5];
    const float* W2 = (const float*)d_in[6];
    const float* b2 = (const float*)d_in[7];
    const float* a2 = (const float*)d_in[8];
    float* out = (float*)d_out;

    __half *fts, *z, *fts2;
    int *cnt;
    int2 *epack;
    cudaGetSymbolAddress((void**)&fts,   g_fts);
    cudaGetSymbolAddress((void**)&z,     g_z);
    cudaGetSymbolAddress((void**)&fts2,  g_fts2);
    cudaGetSymbolAddress((void**)&cnt,   g_cnt);
    cudaGetSymbolAddress((void**)&epack, g_epack);

    const int EB  = (N_EDGES + 255) / 256;
    const int NBK = (N_NODES + 255) / 256;
    const int GB  = (N_NODES + 63) / 64;               // 782 tiles (BM=64)

    // node halves for the seg1/gemm2 pipeline (64-divisible split)
    const int H0 = 25088;
    const int H1 = N_NODES - H0;
    const int G0 = H0 / 64;
    const int G1 = (H1 + 63) / 64;
    const int SGB0 = (H0 * 16 + 255) / 256;
    const int SGB1 = (H1 * 16 + 255) / 256;
    const int SGBF = (N_NODES * 16 + 255) / 256;

    // ---- fork: bucket build on g_s2, concurrent with gemm1 on stream 0 ----
    cudaEventRecord(g_ev_fork, 0);
    cudaStreamWaitEvent(g_s2, g_ev_fork, 0);

    zero_int_kernel<<<NBK, 256, 0, g_s2>>>(cnt, N_NODES);
    fill_kernel<<<EB, 256, 0, g_s2>>>(ei, ew, cnt, epack);
    cudaEventRecord(g_ev_csr, g_s2);

    gemm_mma_kernel<IN_DIM, float><<<GB, 256>>>(x, W1, fts, N_NODES);

    // ---- join: seg1 needs buckets + gemm1 ----
    cudaStreamWaitEvent(0, g_ev_csr, 0);

    // seg1 half0 -> z[0:H0] (fp16); gemm2 half0 (z->fts2) on s2 concurrently
    // with seg1 half1 (reads fts only; fts2 disjoint -> race-free).
    seg_kernel<true><<<SGB0, 256>>>(fts, cnt, epack, b1, a1, z, 0, H0);
    cudaEventRecord(g_ev_sh0, 0);
    cudaStreamWaitEvent(g_s2, g_ev_sh0, 0);
    gemm_mma_kernel<HID, __half><<<G0, 256, 0, g_s2>>>(z, W2, fts2, H0);
    cudaEventRecord(g_ev_g2h0, g_s2);

    seg_kernel<true><<<SGB1, 256>>>(fts, cnt, epack, b1, a1, z, H0, H1);
    gemm_mma_kernel<HID, __half><<<G1, 256>>>(z + (size_t)H0 * HID, W2,
                                              fts2 + (size_t)H0 * HID, H1);

    // seg2 needs both gemm2 halves; writes fp32 to out
    cudaStreamWaitEvent(0, g_ev_g2h0, 0);
    seg_kernel<false><<<SGBF, 256>>>(fts2, cnt, epack, b2, a2, out, 0, N_NODES);
}

// round 15
// speedup vs baseline: 1.2433x; 1.0587x over previous
#include <cuda_runtime.h>
#include <cuda_fp16.h>
#include <cstdint>

#define N_NODES 50000
#define N_EDGES 800000
#define IN_DIM  256
#define HID     128
#define CAP     96          // per-node bucket capacity (Poisson(16) -> P(>=96) ~ 1e-40)

// -------- scratch (device globals; no allocations allowed) ------------------
__device__ __half g_fts [N_NODES * HID];     // gemm1 out, fp16 (read-only in seg1 phase)
__device__ __half g_z   [N_NODES * HID];     // seg1 out / gemm2 in, fp16
__device__ __half g_fts2[N_NODES * HID];     // gemm2 out / seg2 in, fp16
__device__ int    g_cnt[N_NODES];            // per-node edge count
__device__ int2   g_epack[N_NODES * CAP];    // (src, weight-bits) buckets

// -------- streams/events (host-side only; no device memory) -----------------
static cudaStream_t g_s2;
static cudaEvent_t  g_ev_fork, g_ev_csr, g_ev_sh0, g_ev_g2h0;
static struct StreamInit {
    StreamInit() {
        cudaStreamCreateWithFlags(&g_s2, cudaStreamNonBlocking);
        cudaEventCreateWithFlags(&g_ev_fork, cudaEventDisableTiming);
        cudaEventCreateWithFlags(&g_ev_csr,  cudaEventDisableTiming);
        cudaEventCreateWithFlags(&g_ev_sh0,  cudaEventDisableTiming);
        cudaEventCreateWithFlags(&g_ev_g2h0, cudaEventDisableTiming);
    }
} g_stream_init;

// fp16 m16n8k16 MMA, fp32 accumulate
__device__ __forceinline__ void mma_f16(float* d, const uint32_t* a, const uint32_t* b) {
    asm volatile(
        "mma.sync.aligned.m16n8k16.row.col.f32.f16.f16.f32 "
        "{%0,%1,%2,%3}, {%4,%5,%6,%7}, {%8,%9}, {%0,%1,%2,%3};"
        : "+f"(d[0]), "+f"(d[1]), "+f"(d[2]), "+f"(d[3])
        : "r"(a[0]), "r"(a[1]), "r"(a[2]), "r"(a[3]), "r"(b[0]), "r"(b[1]));
}

// 4-value load, fp32 or fp16 source, returns fp32
__device__ __forceinline__ float4 load4(const float* p) {
    return *reinterpret_cast<const float4*>(p);
}
__device__ __forceinline__ float4 load4(const __half* p) {
    uint2 u = *reinterpret_cast<const uint2*>(p);
    __half2 h0 = *reinterpret_cast<__half2*>(&u.x);
    __half2 h1 = *reinterpret_cast<__half2*>(&u.y);
    float2 f0 = __half22float2(h0), f1 = __half22float2(h1);
    return make_float4(f0.x, f0.y, f1.x, f1.y);
}

// load 4 values as packed fp16 (uint2 = 4 halves)
__device__ __forceinline__ uint2 loadh4(const float* p) {
    float4 v = *reinterpret_cast<const float4*>(p);
    __half2 h0 = __floats2half2_rn(v.x, v.y);
    __half2 h1 = __floats2half2_rn(v.z, v.w);
    return make_uint2(*reinterpret_cast<uint32_t*>(&h0), *reinterpret_cast<uint32_t*>(&h1));
}
__device__ __forceinline__ uint2 loadh4(const __half* p) {
    return *reinterpret_cast<const uint2*>(p);
}

// 8 halves (uint4) -> 8 floats, accumulate with weight
__device__ __forceinline__ void acc8(float* acc, uint4 u, float w) {
    __half2 h0 = *reinterpret_cast<__half2*>(&u.x);
    __half2 h1 = *reinterpret_cast<__half2*>(&u.y);
    __half2 h2 = *reinterpret_cast<__half2*>(&u.z);
    __half2 h3 = *reinterpret_cast<__half2*>(&u.w);
    float2 f0 = __half22float2(h0), f1 = __half22float2(h1);
    float2 f2 = __half22float2(h2), f3 = __half22float2(h3);
    acc[0] += w * f0.x; acc[1] += w * f0.y;
    acc[2] += w * f1.x; acc[3] += w * f1.y;
    acc[4] += w * f2.x; acc[5] += w * f2.y;
    acc[6] += w * f3.x; acc[7] += w * f3.y;
}

// ===========================================================================
// bucket build: zero counts -> scatter edges into per-node buckets
// ===========================================================================
__global__ void zero_int_kernel(int* __restrict__ p, int n) {
    int i = blockIdx.x * blockDim.x + threadIdx.x;
    if (i < n) p[i] = 0;
}

__global__ void fill_kernel(const int* __restrict__ ei, const float* __restrict__ ew,
                            int* __restrict__ cnt, int2* __restrict__ epack)
{
    int i = blockIdx.x * blockDim.x + threadIdx.x;
    if (i >= N_EDGES) return;
    int src   = __ldg(&ei[i]);
    int dst   = __ldg(&ei[N_EDGES + i]);
    int wbits = __float_as_int(__ldg(&ew[i]));
    int pos = atomicAdd(&cnt[dst], 1);
    if (pos < CAP)                                  // never triggers; OOB guard
        epack[(size_t)dst * CAP + pos] = make_int2(src, wbits);
}

// ===========================================================================
// fp16 mma.sync GEMM: C[M][128] = A[M][K] @ W[128][K]^T, fp16 output.
// CTA = 64x128 tile (2 CTAs/SM), 8 warps, warp tile 32x32 via m16n8k16.
// SMEM rows of 32 halves padded to 40 (20 words) -> conflict-free frag LDS.
// ===========================================================================
#define ASTR 40   // halves per SMEM row

template <int K, typename AT>
__global__ __launch_bounds__(256, 2) void gemm_mma_kernel(
    const AT* __restrict__ A, const float* __restrict__ W,
    __half* __restrict__ C, int M)
{
    constexpr int NC = K / 32;
    __shared__ __half As[64 * ASTR];
    __shared__ __half Ws[128 * ASTR];

    const int tid  = threadIdx.x;
    const int lane = tid & 31;
    const int w    = tid >> 5;
    const int m0   = blockIdx.x * 64;
    const int wr   = (w & 1) * 32;    // warp row base (0/32)
    const int wc   = (w >> 1) * 32;   // warp col base (0..96)
    const int grp  = lane >> 2;       // 0..7
    const int tig  = lane & 3;        // 0..3

    float acc[2][4][4];
#pragma unroll
    for (int mt = 0; mt < 2; mt++)
#pragma unroll
        for (int nt = 0; nt < 4; nt++)
#pragma unroll
            for (int j = 0; j < 4; j++) acc[mt][nt][j] = 0.f;

    const int lr = tid >> 3;          // 0..31 (tile row slot)
    const int lc = (tid & 7) * 4;     // half-index 0,4,...,28 within chunk

    uint2 pa[2], pw[4];
#pragma unroll
    for (int t = 0; t < 2; t++) {
        int m = m0 + lr + t * 32;
        pa[t] = (m < M) ? loadh4(&A[(size_t)m * K + lc]) : make_uint2(0u, 0u);
    }
#pragma unroll
    for (int t = 0; t < 4; t++)
        pw[t] = loadh4(&W[(size_t)(lr + t * 32) * K + lc]);

#pragma unroll 1
    for (int ch = 0; ch < NC; ch++) {
        if (ch) __syncthreads();
#pragma unroll
        for (int t = 0; t < 2; t++)
            *reinterpret_cast<uint2*>(&As[(lr + t * 32) * ASTR + lc]) = pa[t];
#pragma unroll
        for (int t = 0; t < 4; t++)
            *reinterpret_cast<uint2*>(&Ws[(lr + t * 32) * ASTR + lc]) = pw[t];
        __syncthreads();

        if (ch + 1 < NC) {            // prefetch next chunk (overlaps MMAs)
            const int ko = (ch + 1) * 32 + lc;
#pragma unroll
            for (int t = 0; t < 2; t++) {
                int m = m0 + lr + t * 32;
                pa[t] = (m < M) ? loadh4(&A[(size_t)m * K + ko]) : make_uint2(0u, 0u);
            }
#pragma unroll
            for (int t = 0; t < 4; t++)
                pw[t] = loadh4(&W[(size_t)(lr + t * 32) * K + ko]);
        }

        // ---- MMAs: 2 k16-steps per 32-K chunk ----
#pragma unroll
        for (int ks = 0; ks < 2; ks++) {
            const int c0 = ks * 16 + tig * 2;   // k-col of first half-pair
            uint32_t af[2][4], bf[4][2];
#pragma unroll
            for (int mt = 0; mt < 2; mt++) {
                int r0 = wr + mt * 16 + grp;
                af[mt][0] = *reinterpret_cast<uint32_t*>(&As[r0 * ASTR + c0]);
                af[mt][1] = *reinterpret_cast<uint32_t*>(&As[(r0 + 8) * ASTR + c0]);
                af[mt][2] = *reinterpret_cast<uint32_t*>(&As[r0 * ASTR + c0 + 8]);
                af[mt][3] = *reinterpret_cast<uint32_t*>(&As[(r0 + 8) * ASTR + c0 + 8]);
            }
#pragma unroll
            for (int nt = 0; nt < 4; nt++) {
                int nb = wc + nt * 8 + grp;
                bf[nt][0] = *reinterpret_cast<uint32_t*>(&Ws[nb * ASTR + c0]);
                bf[nt][1] = *reinterpret_cast<uint32_t*>(&Ws[nb * ASTR + c0 + 8]);
            }
#pragma unroll
            for (int mt = 0; mt < 2; mt++)
#pragma unroll
                for (int nt = 0; nt < 4; nt++)
                    mma_f16(acc[mt][nt], af[mt], bf[nt]);
        }
    }

    // epilogue: fp16 store (half2 per fragment pair) — same C layout as tf32
#pragma unroll
    for (int mt = 0; mt < 2; mt++) {
        int r0 = m0 + wr + mt * 16 + grp;
        int r1 = r0 + 8;
#pragma unroll
        for (int nt = 0; nt < 4; nt++) {
            int col = wc + nt * 8 + tig * 2;
            if (r0 < M)
                *reinterpret_cast<__half2*>(&C[(size_t)r0 * 128 + col]) =
                    __floats2half2_rn(acc[mt][nt][0], acc[mt][nt][1]);
            if (r1 < M)
                *reinterpret_cast<__half2*>(&C[(size_t)r1 * 128 + col]) =
                    __floats2half2_rn(acc[mt][nt][2], acc[mt][nt][3]);
        }
    }
}

// ===========================================================================
// Fused segmented gather-sum + bias + PReLU.
// HALF-WARP (16 lanes) per dst node: lane gathers uint4 (8 halves = 16B),
// one warp advances TWO edges per load instruction. Descriptors loaded
// coalesced (16/half-warp) and broadcast via width-16 shfl.
// ===========================================================================
template <bool OUT16>
__global__ __launch_bounds__(256) void seg_kernel(
    const __half* __restrict__ fts,
    const int*    __restrict__ cnt,
    const int2*   __restrict__ epack,
    const float*  __restrict__ b,
    const float*  __restrict__ a,
    void*         __restrict__ out,
    int node_base, int n_nodes)
{
    int hw = (blockIdx.x * blockDim.x + threadIdx.x) >> 4;   // half-warp index
    int hl = threadIdx.x & 15;                               // lane within half
    if (hw >= n_nodes) return;
    const int node = node_base + hw;

    const int deg = min(cnt[node], CAP);
    const int2* ep = epack + (size_t)node * CAP;

    float acc[8];
#pragma unroll
    for (int i = 0; i < 8; i++) acc[i] = 0.f;

#pragma unroll 1
    for (int c0 = 0; c0 < deg; c0 += 16) {
        const int n = min(deg - c0, 16);
        // coalesced 128B load per half-warp: lane e holds edge c0+e
        int2 ed = (hl < n) ? __ldg(&ep[c0 + hl]) : make_int2(0, 0);

        int e = 0;
        for (; e + 3 < n; e += 4) {
            int   s0 = __shfl_sync(0xFFFFFFFFu, ed.x, e,     16);
            int   s1 = __shfl_sync(0xFFFFFFFFu, ed.x, e + 1, 16);
            int   s2 = __shfl_sync(0xFFFFFFFFu, ed.x, e + 2, 16);
            int   s3 = __shfl_sync(0xFFFFFFFFu, ed.x, e + 3, 16);
            float w0 = __int_as_float(__shfl_sync(0xFFFFFFFFu, ed.y, e,     16));
            float w1 = __int_as_float(__shfl_sync(0xFFFFFFFFu, ed.y, e + 1, 16));
            float w2 = __int_as_float(__shfl_sync(0xFFFFFFFFu, ed.y, e + 2, 16));
            float w3 = __int_as_float(__shfl_sync(0xFFFFFFFFu, ed.y, e + 3, 16));
            uint4 v0 = reinterpret_cast<const uint4*>(fts + (size_t)s0 * HID)[hl];
            uint4 v1 = reinterpret_cast<const uint4*>(fts + (size_t)s1 * HID)[hl];
            uint4 v2 = reinterpret_cast<const uint4*>(fts + (size_t)s2 * HID)[hl];
            uint4 v3 = reinterpret_cast<const uint4*>(fts + (size_t)s3 * HID)[hl];
            acc8(acc, v0, w0); acc8(acc, v1, w1);
            acc8(acc, v2, w2); acc8(acc, v3, w3);
        }
        for (; e < n; e++) {
            int   s0 = __shfl_sync(0xFFFFFFFFu, ed.x, e, 16);
            float w0 = __int_as_float(__shfl_sync(0xFFFFFFFFu, ed.y, e, 16));
            uint4 v0 = reinterpret_cast<const uint4*>(fts + (size_t)s0 * HID)[hl];
            acc8(acc, v0, w0);
        }
    }

    float alpha = a[0];
    float4 bb0 = load4(&b[hl * 8]);
    float4 bb1 = load4(&b[hl * 8 + 4]);
    acc[0] += bb0.x; acc[1] += bb0.y; acc[2] += bb0.z; acc[3] += bb0.w;
    acc[4] += bb1.x; acc[5] += bb1.y; acc[6] += bb1.z; acc[7] += bb1.w;
#pragma unroll
    for (int i = 0; i < 8; i++)
        acc[i] = acc[i] >= 0.f ? acc[i] : alpha * acc[i];

    if (OUT16) {
        __half2 h0 = __floats2half2_rn(acc[0], acc[1]);
        __half2 h1 = __floats2half2_rn(acc[2], acc[3]);
        __half2 h2 = __floats2half2_rn(acc[4], acc[5]);
        __half2 h3 = __floats2half2_rn(acc[6], acc[7]);
        uint4 st;
        st.x = *reinterpret_cast<uint32_t*>(&h0);
        st.y = *reinterpret_cast<uint32_t*>(&h1);
        st.z = *reinterpret_cast<uint32_t*>(&h2);
        st.w = *reinterpret_cast<uint32_t*>(&h3);
        reinterpret_cast<uint4*>(reinterpret_cast<__half*>(out) + (size_t)node * HID)[hl] = st;
    } else {
        float* op = reinterpret_cast<float*>(out) + (size_t)node * HID + hl * 8;
        *reinterpret_cast<float4*>(op)     = make_float4(acc[0], acc[1], acc[2], acc[3]);
        *reinterpret_cast<float4*>(op + 4) = make_float4(acc[4], acc[5], acc[6], acc[7]);
    }
}

// ===========================================================================
extern "C" void kernel_launch(void* const* d_in, const int* in_sizes, int n_in,
                              void* d_out, int out_size)
{
    const float* x  = (const float*)d_in[0];
    const int*   ei = (const int*)  d_in[1];
    const float* ew = (const float*)d_in[2];
    const float* W1 = (const float*)d_in[3];
    const float* b1 = (const float*)d_in[4];
    const float* a1 = (const float*)d_in[5];
    const float* W2 = (const float*)d_in[6];
    const float* b2 = (const float*)d_in[7];
    const float* a2 = (const float*)d_in[8];
    float* out = (float*)d_out;

    __half *fts, *z, *fts2;
    int *cnt;
    int2 *epack;
    cudaGetSymbolAddress((void**)&fts,   g_fts);
    cudaGetSymbolAddress((void**)&z,     g_z);
    cudaGetSymbolAddress((void**)&fts2,  g_fts2);
    cudaGetSymbolAddress((void**)&cnt,   g_cnt);
    cudaGetSymbolAddress((void**)&epack, g_epack);

    const int EB  = (N_EDGES + 255) / 256;
    const int NBK = (N_NODES + 255) / 256;
    const int GB  = (N_NODES + 63) / 64;               // 782 tiles (BM=64)

    // node halves for the seg1/gemm2 pipeline (64-divisible split)
    const int H0 = 25088;
    const int H1 = N_NODES - H0;
    const int G0 = H0 / 64;
    const int G1 = (H1 + 63) / 64;
    const int SGB0 = (H0 * 16 + 255) / 256;
    const int SGB1 = (H1 * 16 + 255) / 256;
    const int SGBF = (N_NODES * 16 + 255) / 256;

    // ---- fork: bucket build on g_s2, concurrent with gemm1 on stream 0 ----
    cudaEventRecord(g_ev_fork, 0);
    cudaStreamWaitEvent(g_s2, g_ev_fork, 0);

    zero_int_kernel<<<NBK, 256, 0, g_s2>>>(cnt, N_NODES);
    fill_kernel<<<EB, 256, 0, g_s2>>>(ei, ew, cnt, epack);
    cudaEventRecord(g_ev_csr, g_s2);

    gemm_mma_kernel<IN_DIM, float><<<GB, 256>>>(x, W1, fts, N_NODES);

    // ---- join: seg1 needs buckets + gemm1 ----
    cudaStreamWaitEvent(0, g_ev_csr, 0);

    // seg1 half0 -> z[0:H0] (fp16); gemm2 half0 (z->fts2) on s2 concurrently
    // with seg1 half1 (reads fts only; fts2 disjoint -> race-free).
    seg_kernel<true><<<SGB0, 256>>>(fts, cnt, epack, b1, a1, z, 0, H0);
    cudaEventRecord(g_ev_sh0, 0);
    cudaStreamWaitEvent(g_s2, g_ev_sh0, 0);
    gemm_mma_kernel<HID, __half><<<G0, 256, 0, g_s2>>>(z, W2, fts2, H0);
    cudaEventRecord(g_ev_g2h0, g_s2);

    seg_kernel<true><<<SGB1, 256>>>(fts, cnt, epack, b1, a1, z, H0, H1);
    gemm_mma_kernel<HID, __half><<<G1, 256>>>(z + (size_t)H0 * HID, W2,
                                              fts2 + (size_t)H0 * HID, H1);

    // seg2 needs both gemm2 halves; writes fp32 to out
    cudaStreamWaitEvent(0, g_ev_g2h0, 0);
    seg_kernel<false><<<SGBF, 256>>>(fts2, cnt, epack, b2, a2, out, 0, N_NODES);
}

// round 16
// speedup vs baseline: 1.2677x; 1.0196x over previous
#include <cuda_runtime.h>
#include <cuda_fp16.h>
#include <cstdint>

#define N_NODES 50000
#define N_EDGES 800000
#define IN_DIM  256
#define HID     128
#define CAP     96          // per-node bucket capacity (Poisson(16) -> P(>=96) ~ 1e-40)

// -------- scratch (device globals; no allocations allowed) ------------------
__device__ __half g_fts [N_NODES * HID];     // gemm1 out, fp16 (read-only in seg1 phase)
__device__ __half g_z   [N_NODES * HID];     // seg1 out / gemm2 in, fp16
__device__ __half g_fts2[N_NODES * HID];     // gemm2 out / seg2 in, fp16
__device__ int    g_cnt[N_NODES];            // per-node edge count
__device__ int2   g_epack[N_NODES * CAP];    // (src, weight-bits) buckets

// -------- streams/events (host-side only; no device memory) -----------------
static cudaStream_t g_s2;
static cudaEvent_t  g_ev_fork, g_ev_csr, g_ev_sh0, g_ev_g2h0;
static struct StreamInit {
    StreamInit() {
        cudaStreamCreateWithFlags(&g_s2, cudaStreamNonBlocking);
        cudaEventCreateWithFlags(&g_ev_fork, cudaEventDisableTiming);
        cudaEventCreateWithFlags(&g_ev_csr,  cudaEventDisableTiming);
        cudaEventCreateWithFlags(&g_ev_sh0,  cudaEventDisableTiming);
        cudaEventCreateWithFlags(&g_ev_g2h0, cudaEventDisableTiming);
    }
} g_stream_init;

// fp16 m16n8k16 MMA, fp32 accumulate
__device__ __forceinline__ void mma_f16(float* d, const uint32_t* a, const uint32_t* b) {
    asm volatile(
        "mma.sync.aligned.m16n8k16.row.col.f32.f16.f16.f32 "
        "{%0,%1,%2,%3}, {%4,%5,%6,%7}, {%8,%9}, {%0,%1,%2,%3};"
        : "+f"(d[0]), "+f"(d[1]), "+f"(d[2]), "+f"(d[3])
        : "r"(a[0]), "r"(a[1]), "r"(a[2]), "r"(a[3]), "r"(b[0]), "r"(b[1]));
}

// 4-value load, fp32 or fp16 source, returns fp32
__device__ __forceinline__ float4 load4(const float* p) {
    return *reinterpret_cast<const float4*>(p);
}
__device__ __forceinline__ float4 load4(const __half* p) {
    uint2 u = *reinterpret_cast<const uint2*>(p);
    __half2 h0 = *reinterpret_cast<__half2*>(&u.x);
    __half2 h1 = *reinterpret_cast<__half2*>(&u.y);
    float2 f0 = __half22float2(h0), f1 = __half22float2(h1);
    return make_float4(f0.x, f0.y, f1.x, f1.y);
}

// load 4 values as packed fp16 (uint2 = 4 halves)
__device__ __forceinline__ uint2 loadh4(const float* p) {
    float4 v = *reinterpret_cast<const float4*>(p);
    __half2 h0 = __floats2half2_rn(v.x, v.y);
    __half2 h1 = __floats2half2_rn(v.z, v.w);
    return make_uint2(*reinterpret_cast<uint32_t*>(&h0), *reinterpret_cast<uint32_t*>(&h1));
}
__device__ __forceinline__ uint2 loadh4(const __half* p) {
    return *reinterpret_cast<const uint2*>(p);
}

// 8 halves (uint4) -> 8 floats, accumulate with fp32 weight (exact path)
__device__ __forceinline__ void acc8(float* acc, uint4 u, float w) {
    __half2 h0 = *reinterpret_cast<__half2*>(&u.x);
    __half2 h1 = *reinterpret_cast<__half2*>(&u.y);
    __half2 h2 = *reinterpret_cast<__half2*>(&u.z);
    __half2 h3 = *reinterpret_cast<__half2*>(&u.w);
    float2 f0 = __half22float2(h0), f1 = __half22float2(h1);
    float2 f2 = __half22float2(h2), f3 = __half22float2(h3);
    acc[0] += w * f0.x; acc[1] += w * f0.y;
    acc[2] += w * f1.x; acc[3] += w * f1.y;
    acc[4] += w * f2.x; acc[5] += w * f2.y;
    acc[6] += w * f3.x; acc[7] += w * f3.y;
}

// HFMA2: hacc[i] += wh * v.h2[i]
__device__ __forceinline__ void hacc8(__half2* hacc, uint4 u, __half2 wh) {
    hacc[0] = __hfma2(wh, *reinterpret_cast<__half2*>(&u.x), hacc[0]);
    hacc[1] = __hfma2(wh, *reinterpret_cast<__half2*>(&u.y), hacc[1]);
    hacc[2] = __hfma2(wh, *reinterpret_cast<__half2*>(&u.z), hacc[2]);
    hacc[3] = __hfma2(wh, *reinterpret_cast<__half2*>(&u.w), hacc[3]);
}

// ===========================================================================
// bucket build: zero counts -> scatter edges into per-node buckets
// ===========================================================================
__global__ void zero_int_kernel(int* __restrict__ p, int n) {
    int i = blockIdx.x * blockDim.x + threadIdx.x;
    if (i < n) p[i] = 0;
}

__global__ void fill_kernel(const int* __restrict__ ei, const float* __restrict__ ew,
                            int* __restrict__ cnt, int2* __restrict__ epack)
{
    int i = blockIdx.x * blockDim.x + threadIdx.x;
    if (i >= N_EDGES) return;
    int src   = __ldg(&ei[i]);
    int dst   = __ldg(&ei[N_EDGES + i]);
    int wbits = __float_as_int(__ldg(&ew[i]));
    int pos = atomicAdd(&cnt[dst], 1);
    if (pos < CAP)                                  // never triggers; OOB guard
        epack[(size_t)dst * CAP + pos] = make_int2(src, wbits);
}

// ===========================================================================
// fp16 mma.sync GEMM: C[M][128] = A[M][K] @ W[128][K]^T, fp16 output.
// CTA = 64x128 tile (2 CTAs/SM), 8 warps, warp tile 32x32 via m16n8k16.
// SMEM rows of 32 halves padded to 40 (20 words) -> conflict-free frag LDS.
// ===========================================================================
#define ASTR 40   // halves per SMEM row

template <int K, typename AT>
__global__ __launch_bounds__(256, 2) void gemm_mma_kernel(
    const AT* __restrict__ A, const float* __restrict__ W,
    __half* __restrict__ C, int M)
{
    constexpr int NC = K / 32;
    __shared__ __half As[64 * ASTR];
    __shared__ __half Ws[128 * ASTR];

    const int tid  = threadIdx.x;
    const int lane = tid & 31;
    const int w    = tid >> 5;
    const int m0   = blockIdx.x * 64;
    const int wr   = (w & 1) * 32;    // warp row base (0/32)
    const int wc   = (w >> 1) * 32;   // warp col base (0..96)
    const int grp  = lane >> 2;       // 0..7
    const int tig  = lane & 3;        // 0..3

    float acc[2][4][4];
#pragma unroll
    for (int mt = 0; mt < 2; mt++)
#pragma unroll
        for (int nt = 0; nt < 4; nt++)
#pragma unroll
            for (int j = 0; j < 4; j++) acc[mt][nt][j] = 0.f;

    const int lr = tid >> 3;          // 0..31 (tile row slot)
    const int lc = (tid & 7) * 4;     // half-index 0,4,...,28 within chunk

    uint2 pa[2], pw[4];
#pragma unroll
    for (int t = 0; t < 2; t++) {
        int m = m0 + lr + t * 32;
        pa[t] = (m < M) ? loadh4(&A[(size_t)m * K + lc]) : make_uint2(0u, 0u);
    }
#pragma unroll
    for (int t = 0; t < 4; t++)
        pw[t] = loadh4(&W[(size_t)(lr + t * 32) * K + lc]);

#pragma unroll 1
    for (int ch = 0; ch < NC; ch++) {
        if (ch) __syncthreads();
#pragma unroll
        for (int t = 0; t < 2; t++)
            *reinterpret_cast<uint2*>(&As[(lr + t * 32) * ASTR + lc]) = pa[t];
#pragma unroll
        for (int t = 0; t < 4; t++)
            *reinterpret_cast<uint2*>(&Ws[(lr + t * 32) * ASTR + lc]) = pw[t];
        __syncthreads();

        if (ch + 1 < NC) {            // prefetch next chunk (overlaps MMAs)
            const int ko = (ch + 1) * 32 + lc;
#pragma unroll
            for (int t = 0; t < 2; t++) {
                int m = m0 + lr + t * 32;
                pa[t] = (m < M) ? loadh4(&A[(size_t)m * K + ko]) : make_uint2(0u, 0u);
            }
#pragma unroll
            for (int t = 0; t < 4; t++)
                pw[t] = loadh4(&W[(size_t)(lr + t * 32) * K + ko]);
        }

        // ---- MMAs: 2 k16-steps per 32-K chunk ----
#pragma unroll
        for (int ks = 0; ks < 2; ks++) {
            const int c0 = ks * 16 + tig * 2;   // k-col of first half-pair
            uint32_t af[2][4], bf[4][2];
#pragma unroll
            for (int mt = 0; mt < 2; mt++) {
                int r0 = wr + mt * 16 + grp;
                af[mt][0] = *reinterpret_cast<uint32_t*>(&As[r0 * ASTR + c0]);
                af[mt][1] = *reinterpret_cast<uint32_t*>(&As[(r0 + 8) * ASTR + c0]);
                af[mt][2] = *reinterpret_cast<uint32_t*>(&As[r0 * ASTR + c0 + 8]);
                af[mt][3] = *reinterpret_cast<uint32_t*>(&As[(r0 + 8) * ASTR + c0 + 8]);
            }
#pragma unroll
            for (int nt = 0; nt < 4; nt++) {
                int nb = wc + nt * 8 + grp;
                bf[nt][0] = *reinterpret_cast<uint32_t*>(&Ws[nb * ASTR + c0]);
                bf[nt][1] = *reinterpret_cast<uint32_t*>(&Ws[nb * ASTR + c0 + 8]);
            }
#pragma unroll
            for (int mt = 0; mt < 2; mt++)
#pragma unroll
                for (int nt = 0; nt < 4; nt++)
                    mma_f16(acc[mt][nt], af[mt], bf[nt]);
        }
    }

    // epilogue: fp16 store (half2 per fragment pair)
#pragma unroll
    for (int mt = 0; mt < 2; mt++) {
        int r0 = m0 + wr + mt * 16 + grp;
        int r1 = r0 + 8;
#pragma unroll
        for (int nt = 0; nt < 4; nt++) {
            int col = wc + nt * 8 + tig * 2;
            if (r0 < M)
                *reinterpret_cast<__half2*>(&C[(size_t)r0 * 128 + col]) =
                    __floats2half2_rn(acc[mt][nt][0], acc[mt][nt][1]);
            if (r1 < M)
                *reinterpret_cast<__half2*>(&C[(size_t)r1 * 128 + col]) =
                    __floats2half2_rn(acc[mt][nt][2], acc[mt][nt][3]);
        }
    }
}

// ===========================================================================
// Fused segmented gather-sum + bias + PReLU.
// HALF-WARP (16 lanes) per dst node. 4-edge groups accumulate in half2
// (HFMA2), folded to fp32 per group: per-edge issue drops ~19 -> ~12 slots.
// Remainder edges (<4) use the exact fp32 path.
// ===========================================================================
template <bool OUT16>
__global__ __launch_bounds__(256) void seg_kernel(
    const __half* __restrict__ fts,
    const int*    __restrict__ cnt,
    const int2*   __restrict__ epack,
    const float*  __restrict__ b,
    const float*  __restrict__ a,
    void*         __restrict__ out,
    int node_base, int n_nodes)
{
    int hw = (blockIdx.x * blockDim.x + threadIdx.x) >> 4;   // half-warp index
    int hl = threadIdx.x & 15;                               // lane within half
    if (hw >= n_nodes) return;
    const int node = node_base + hw;

    const int deg = min(cnt[node], CAP);
    const int2* ep = epack + (size_t)node * CAP;

    float acc[8];
#pragma unroll
    for (int i = 0; i < 8; i++) acc[i] = 0.f;

#pragma unroll 1
    for (int c0 = 0; c0 < deg; c0 += 16) {
        const int n = min(deg - c0, 16);
        // coalesced 128B load per half-warp: lane e holds edge c0+e
        int2 ed = (hl < n) ? __ldg(&ep[c0 + hl]) : make_int2(0, 0);

        int e = 0;
        for (; e + 3 < n; e += 4) {
            int s[4]; __half2 wh[4];
#pragma unroll
            for (int j = 0; j < 4; j++) {
                s[j] = __shfl_sync(0xFFFFFFFFu, ed.x, e + j, 16);
                float wj = __int_as_float(__shfl_sync(0xFFFFFFFFu, ed.y, e + j, 16));
                wh[j] = __float2half2_rn(wj);
            }
            uint4 v[4];
#pragma unroll
            for (int j = 0; j < 4; j++)
                v[j] = reinterpret_cast<const uint4*>(fts + (size_t)s[j] * HID)[hl];

            __half2 hacc[4];
            hacc[0] = __hmul2(wh[0], *reinterpret_cast<__half2*>(&v[0].x));
            hacc[1] = __hmul2(wh[0], *reinterpret_cast<__half2*>(&v[0].y));
            hacc[2] = __hmul2(wh[0], *reinterpret_cast<__half2*>(&v[0].z));
            hacc[3] = __hmul2(wh[0], *reinterpret_cast<__half2*>(&v[0].w));
#pragma unroll
            for (int j = 1; j < 4; j++) hacc8(hacc, v[j], wh[j]);

            // fold group to fp32
#pragma unroll
            for (int i = 0; i < 4; i++) {
                float2 f = __half22float2(hacc[i]);
                acc[i * 2]     += f.x;
                acc[i * 2 + 1] += f.y;
            }
        }
        for (; e < n; e++) {          // exact fp32 remainder
            int   s0 = __shfl_sync(0xFFFFFFFFu, ed.x, e, 16);
            float w0 = __int_as_float(__shfl_sync(0xFFFFFFFFu, ed.y, e, 16));
            uint4 v0 = reinterpret_cast<const uint4*>(fts + (size_t)s0 * HID)[hl];
            acc8(acc, v0, w0);
        }
    }

    float alpha = a[0];
    float4 bb0 = load4(&b[hl * 8]);
    float4 bb1 = load4(&b[hl * 8 + 4]);
    acc[0] += bb0.x; acc[1] += bb0.y; acc[2] += bb0.z; acc[3] += bb0.w;
    acc[4] += bb1.x; acc[5] += bb1.y; acc[6] += bb1.z; acc[7] += bb1.w;
#pragma unroll
    for (int i = 0; i < 8; i++)
        acc[i] = acc[i] >= 0.f ? acc[i] : alpha * acc[i];

    if (OUT16) {
        __half2 h0 = __floats2half2_rn(acc[0], acc[1]);
        __half2 h1 = __floats2half2_rn(acc[2], acc[3]);
        __half2 h2 = __floats2half2_rn(acc[4], acc[5]);
        __half2 h3 = __floats2half2_rn(acc[6], acc[7]);
        uint4 st;
        st.x = *reinterpret_cast<uint32_t*>(&h0);
        st.y = *reinterpret_cast<uint32_t*>(&h1);
        st.z = *reinterpret_cast<uint32_t*>(&h2);
        st.w = *reinterpret_cast<uint32_t*>(&h3);
        reinterpret_cast<uint4*>(reinterpret_cast<__half*>(out) + (size_t)node * HID)[hl] = st;
    } else {
        float* op = reinterpret_cast<float*>(out) + (size_t)node * HID + hl * 8;
        *reinterpret_cast<float4*>(op)     = make_float4(acc[0], acc[1], acc[2], acc[3]);
        *reinterpret_cast<float4*>(op + 4) = make_float4(acc[4], acc[5], acc[6], acc[7]);
    }
}

// ===========================================================================
extern "C" void kernel_launch(void* const* d_in, const int* in_sizes, int n_in,
                              void* d_out, int out_size)
{
    const float* x  = (const float*)d_in[0];
    const int*   ei = (const int*)  d_in[1];
    const float* ew = (const float*)d_in[2];
    const float* W1 = (const float*)d_in[3];
    const float* b1 = (const float*)d_in[4];
    const float* a1 = (const float*)d_in[5];
    const float* W2 = (const float*)d_in[6];
    const float* b2 = (const float*)d_in[7];
    const float* a2 = (const float*)d_in[8];
    float* out = (float*)d_out;

    __half *fts, *z, *fts2;
    int *cnt;
    int2 *epack;
    cudaGetSymbolAddress((void**)&fts,   g_fts);
    cudaGetSymbolAddress((void**)&z,     g_z);
    cudaGetSymbolAddress((void**)&fts2,  g_fts2);
    cudaGetSymbolAddress((void**)&cnt,   g_cnt);
    cudaGetSymbolAddress((void**)&epack, g_epack);

    const int EB  = (N_EDGES + 255) / 256;
    const int NBK = (N_NODES + 255) / 256;
    const int GB  = (N_NODES + 63) / 64;               // 782 tiles (BM=64)

    // node halves for the seg1/gemm2 pipeline (64-divisible split)
    const int H0 = 25088;
    const int H1 = N_NODES - H0;
    const int G0 = H0 / 64;
    const int G1 = (H1 + 63) / 64;
    const int SGB0 = (H0 * 16 + 255) / 256;
    const int SGB1 = (H1 * 16 + 255) / 256;
    const int SGBF = (N_NODES * 16 + 255) / 256;

    // ---- fork: bucket build on g_s2, concurrent with gemm1 on stream 0 ----
    cudaEventRecord(g_ev_fork, 0);
    cudaStreamWaitEvent(g_s2, g_ev_fork, 0);

    zero_int_kernel<<<NBK, 256, 0, g_s2>>>(cnt, N_NODES);
    fill_kernel<<<EB, 256, 0, g_s2>>>(ei, ew, cnt, epack);
    cudaEventRecord(g_ev_csr, g_s2);

    gemm_mma_kernel<IN_DIM, float><<<GB, 256>>>(x, W1, fts, N_NODES);

    // ---- join: seg1 needs buckets + gemm1 ----
    cudaStreamWaitEvent(0, g_ev_csr, 0);

    // seg1 half0 -> z[0:H0] (fp16); gemm2 half0 (z->fts2) on s2 concurrently
    // with seg1 half1 (reads fts only; fts2 disjoint -> race-free).
    seg_kernel<true><<<SGB0, 256>>>(fts, cnt, epack, b1, a1, z, 0, H0);
    cudaEventRecord(g_ev_sh0, 0);
    cudaStreamWaitEvent(g_s2, g_ev_sh0, 0);
    gemm_mma_kernel<HID, __half><<<G0, 256, 0, g_s2>>>(z, W2, fts2, H0);
    cudaEventRecord(g_ev_g2h0, g_s2);

    seg_kernel<true><<<SGB1, 256>>>(fts, cnt, epack, b1, a1, z, H0, H1);
    gemm_mma_kernel<HID, __half><<<G1, 256>>>(z + (size_t)H0 * HID, W2,
                                              fts2 + (size_t)H0 * HID, H1);

    // seg2 needs both gemm2 halves; writes fp32 to out
    cudaStreamWaitEvent(0, g_ev_g2h0, 0);
    seg_kernel<false><<<SGBF, 256>>>(fts2, cnt, epack, b2, a2, out, 0, N_NODES);
}